// round 1
// baseline (speedup 1.0000x reference)
#include <cuda_runtime.h>

#define N_NODES 100000
#define N_EDGES 600000
#define F0 128
#define F1 64
#define F2 32
#define SCAN_BLK 1024
#define NB_SCAN ((N_NODES + SCAN_BLK - 1) / SCAN_BLK)   // 98

// ---------------- scratch (static device globals; no allocation) ----------------
__device__ float g_h1[N_NODES * F1];       // X @ W1
__device__ float g_a1[N_NODES * F1];       // relu(agg1 + b1)
__device__ float g_h2[N_NODES * F2];       // a1 @ W2
__device__ int   g_deg[N_NODES];           // in-edge count (without self loop)
__device__ float g_dinv[N_NODES];          // rsqrt(deg+1)
__device__ int   g_rowoff[N_NODES + 1];    // CSR row offsets (in-edges)
__device__ int   g_cursor[N_NODES];        // CSR fill cursors
__device__ int   g_col[N_EDGES];           // CSR column (src) indices
__device__ int   g_bsum[NB_SCAN];          // scan block sums

// ---------------- preprocessing ----------------
__global__ void k_clear() {
    int i = blockIdx.x * blockDim.x + threadIdx.x;
    if (i < N_NODES) { g_deg[i] = 0; g_cursor[i] = 0; }
}

__global__ void k_deg(const int* __restrict__ dst) {
    int e = blockIdx.x * blockDim.x + threadIdx.x;
    if (e < N_EDGES) atomicAdd(&g_deg[dst[e]], 1);
}

__global__ void k_dinv() {
    int i = blockIdx.x * blockDim.x + threadIdx.x;
    if (i < N_NODES) g_dinv[i] = rsqrtf((float)(g_deg[i] + 1));
}

// 3-kernel exclusive scan of g_deg -> g_rowoff
__global__ void k_scan1() {
    __shared__ int s[SCAN_BLK];
    int idx = blockIdx.x * SCAN_BLK + threadIdx.x;
    int v = (idx < N_NODES) ? g_deg[idx] : 0;
    s[threadIdx.x] = v;
    __syncthreads();
    // Hillis-Steele inclusive scan
    for (int o = 1; o < SCAN_BLK; o <<= 1) {
        int t = (threadIdx.x >= o) ? s[threadIdx.x - o] : 0;
        __syncthreads();
        s[threadIdx.x] += t;
        __syncthreads();
    }
    if (idx < N_NODES) g_rowoff[idx] = s[threadIdx.x] - v;  // exclusive within block
    if (threadIdx.x == SCAN_BLK - 1) g_bsum[blockIdx.x] = s[SCAN_BLK - 1];
}

__global__ void k_scan2() {  // single thread: scan 98 block sums
    int run = 0;
    for (int b = 0; b < NB_SCAN; b++) {
        int t = g_bsum[b];
        g_bsum[b] = run;
        run += t;
    }
}

__global__ void k_scan3() {
    int idx = blockIdx.x * blockDim.x + threadIdx.x;
    if (idx < N_NODES) g_rowoff[idx] += g_bsum[idx / SCAN_BLK];
    if (idx == 0) g_rowoff[N_NODES] = N_EDGES;
}

__global__ void k_csr_fill(const int* __restrict__ src, const int* __restrict__ dst) {
    int e = blockIdx.x * blockDim.x + threadIdx.x;
    if (e < N_EDGES) {
        int d = dst[e];
        int p = atomicAdd(&g_cursor[d], 1);
        g_col[g_rowoff[d] + p] = src[e];
    }
}

// ---------------- GEMM 1: h1 = X[N,128] @ W1[128,64] ----------------
__global__ __launch_bounds__(256) void k_gemm1(const float* __restrict__ x,
                                               const float* __restrict__ W1) {
    __shared__ float Ws[F0 * F1];  // 32 KB
    for (int i = threadIdx.x; i < F0 * F1; i += 256) Ws[i] = W1[i];
    __syncthreads();

    int r = blockIdx.x * 256 + threadIdx.x;
    if (r >= N_NODES) return;

    float acc[F1];
#pragma unroll
    for (int n = 0; n < F1; n++) acc[n] = 0.f;

    const float4* x4 = (const float4*)(x + (size_t)r * F0);
#pragma unroll 8
    for (int k4 = 0; k4 < F0 / 4; k4++) {
        float4 xv = x4[k4];
        const float* w0 = &Ws[(k4 * 4 + 0) * F1];
        const float* w1 = &Ws[(k4 * 4 + 1) * F1];
        const float* w2 = &Ws[(k4 * 4 + 2) * F1];
        const float* w3 = &Ws[(k4 * 4 + 3) * F1];
#pragma unroll
        for (int n = 0; n < F1; n++) {
            acc[n] = fmaf(xv.x, w0[n], acc[n]);
            acc[n] = fmaf(xv.y, w1[n], acc[n]);
            acc[n] = fmaf(xv.z, w2[n], acc[n]);
            acc[n] = fmaf(xv.w, w3[n], acc[n]);
        }
    }
    float4* out = (float4*)(g_h1 + (size_t)r * F1);
#pragma unroll
    for (int n = 0; n < F1 / 4; n++)
        out[n] = make_float4(acc[4*n], acc[4*n+1], acc[4*n+2], acc[4*n+3]);
}

// ---------------- Aggregation 1: a1 = relu(norm-agg(h1) + b1) ----------------
__global__ __launch_bounds__(256) void k_agg1(const float* __restrict__ b1) {
    int gw = (blockIdx.x * blockDim.x + threadIdx.x) >> 5;
    int lane = threadIdx.x & 31;
    if (gw >= N_NODES) return;

    float di = g_dinv[gw];
    const float* hr = g_h1 + (size_t)gw * F1;
    float sl = di * di;                      // self-loop norm
    float a0 = sl * hr[lane];
    float a1 = sl * hr[lane + 32];

    int beg = g_rowoff[gw], end = g_rowoff[gw + 1];
    for (int e = beg; e < end; e++) {
        int s = g_col[e];                    // broadcast load
        float w = g_dinv[s] * di;
        const float* hs = g_h1 + (size_t)s * F1;
        a0 = fmaf(w, hs[lane], a0);
        a1 = fmaf(w, hs[lane + 32], a1);
    }
    float* o = g_a1 + (size_t)gw * F1;
    o[lane]      = fmaxf(a0 + b1[lane], 0.f);
    o[lane + 32] = fmaxf(a1 + b1[lane + 32], 0.f);
}

// ---------------- GEMM 2: h2 = a1[N,64] @ W2[64,32] ----------------
__global__ __launch_bounds__(256) void k_gemm2(const float* __restrict__ W2) {
    __shared__ float Ws[F1 * F2];  // 8 KB
    for (int i = threadIdx.x; i < F1 * F2; i += 256) Ws[i] = W2[i];
    __syncthreads();

    int r = blockIdx.x * 256 + threadIdx.x;
    if (r >= N_NODES) return;

    float acc[F2];
#pragma unroll
    for (int n = 0; n < F2; n++) acc[n] = 0.f;

    const float4* x4 = (const float4*)(g_a1 + (size_t)r * F1);
#pragma unroll
    for (int k4 = 0; k4 < F1 / 4; k4++) {
        float4 xv = x4[k4];
        const float* w0 = &Ws[(k4 * 4 + 0) * F2];
        const float* w1 = &Ws[(k4 * 4 + 1) * F2];
        const float* w2 = &Ws[(k4 * 4 + 2) * F2];
        const float* w3 = &Ws[(k4 * 4 + 3) * F2];
#pragma unroll
        for (int n = 0; n < F2; n++) {
            acc[n] = fmaf(xv.x, w0[n], acc[n]);
            acc[n] = fmaf(xv.y, w1[n], acc[n]);
            acc[n] = fmaf(xv.z, w2[n], acc[n]);
            acc[n] = fmaf(xv.w, w3[n], acc[n]);
        }
    }
    float4* out = (float4*)(g_h2 + (size_t)r * F2);
#pragma unroll
    for (int n = 0; n < F2 / 4; n++)
        out[n] = make_float4(acc[4*n], acc[4*n+1], acc[4*n+2], acc[4*n+3]);
}

// ---------------- Aggregation 2 + classifier (fused) ----------------
__global__ __launch_bounds__(256) void k_agg2(const float* __restrict__ b2,
                                              const float* __restrict__ Wc,
                                              const float* __restrict__ bc,
                                              float* __restrict__ out) {
    int gw = (blockIdx.x * blockDim.x + threadIdx.x) >> 5;
    int lane = threadIdx.x & 31;
    if (gw >= N_NODES) return;

    float di = g_dinv[gw];
    float a = di * di * g_h2[(size_t)gw * F2 + lane];

    int beg = g_rowoff[gw], end = g_rowoff[gw + 1];
    for (int e = beg; e < end; e++) {
        int s = g_col[e];
        float w = g_dinv[s] * di;
        a = fmaf(w, g_h2[(size_t)s * F2 + lane], a);
    }
    float v = fmaxf(a + b2[lane], 0.f) * Wc[lane];
#pragma unroll
    for (int o = 16; o > 0; o >>= 1) v += __shfl_down_sync(0xffffffffu, v, o);
    if (lane == 0) out[gw] = v + bc[0];
}

// ---------------- launch ----------------
extern "C" void kernel_launch(void* const* d_in, const int* in_sizes, int n_in,
                              void* d_out, int out_size) {
    const float* x  = (const float*)d_in[0];
    const int*   ei = (const int*)d_in[1];   // edge_index [2, E] (int32: jax x64 disabled)
    const float* W1 = (const float*)d_in[2];
    const float* b1 = (const float*)d_in[3];
    const float* W2 = (const float*)d_in[4];
    const float* b2 = (const float*)d_in[5];
    const float* Wc = (const float*)d_in[6];
    const float* bc = (const float*)d_in[7];
    float* out = (float*)d_out;

    const int* src = ei;
    const int* dst = ei + N_EDGES;

    const int NBn = (N_NODES + 255) / 256;                 // node-parallel blocks
    const int NBe = (N_EDGES + 255) / 256;                 // edge-parallel blocks
    const int NBw = (N_NODES * 32 + 255) / 256;            // warp-per-node blocks

    k_clear<<<NBn, 256>>>();
    k_deg<<<NBe, 256>>>(dst);
    k_dinv<<<NBn, 256>>>();
    k_scan1<<<NB_SCAN, SCAN_BLK>>>();
    k_scan2<<<1, 1>>>();
    k_scan3<<<NBn, 256>>>();
    k_csr_fill<<<NBe, 256>>>(src, dst);

    k_gemm1<<<NBn, 256>>>(x, W1);
    k_agg1<<<NBw, 256>>>(b1);
    k_gemm2<<<NBn, 256>>>(W2);
    k_agg2<<<NBw, 256>>>(b2, Wc, bc, out);
}